// round 2
// baseline (speedup 1.0000x reference)
#include <cuda_runtime.h>
#include <cstdint>

#define B_ 32
#define I_ 1152
#define O_ 10
#define D_ 16
#define H_ 10
#define S_ 922
#define T_ 512          // threads per block

__device__ int g_is64;

// ---------------------------------------------------------------------------
// Detect int64 vs int32 sample_idx: values < 1152, so int64 => odd words all 0
// ---------------------------------------------------------------------------
__global__ void detect_kernel(const unsigned* __restrict__ idx32) {
    __shared__ unsigned red[256];
    unsigned v = 0;
    for (int t = threadIdx.x; t < 2048; t += 256) v |= idx32[2 * t + 1];
    red[threadIdx.x] = v;
    __syncthreads();
    for (int s = 128; s > 0; s >>= 1) {
        if (threadIdx.x < (unsigned)s) red[threadIdx.x] |= red[threadIdx.x + s];
        __syncthreads();
    }
    if (threadIdx.x == 0) g_is64 = (red[0] == 0u) ? 1 : 0;
}

// ---------------------------------------------------------------------------
// Fused kernel: one block per (b,o). Everything staged in shared memory.
//   phase0: load u[b,:,o,:] slice -> smem, partial squares -> vn
//   phase0b: zero smem mask, scatter sample_idx bits via smem atomicOr
//   phase1: masked weighted accumulation -> Mu[h][d]
//   phase2: loss[h] = sum_i sqrt(vn_i^2 - 2 u_i.Mu_h + |Mu_h|^2), argmin
//   emit Mu[h*]
// Dynamic smem: u 73728B + vn 4608B + scratch 18432B = 96768B -> 2 blocks/SM
// ---------------------------------------------------------------------------
__global__ void __launch_bounds__(T_) fused_kernel(const float* __restrict__ u,
                                                   const int* __restrict__ idx,
                                                   float* __restrict__ out) {
    extern __shared__ float sm[];
    float*    s_u   = sm;                         // [1152][16]
    float*    s_vn  = sm + I_ * D_;               // [1152]
    float*    s_scr = s_vn + I_;                  // 4608 floats, multi-use
    unsigned* s_mask = (unsigned*)s_scr;          // [1152]  (after vn done)
    float*    s_num = s_scr + 1280;               // [16][10][16] = 2560
    float*    s_den = s_scr + 3840;               // [16][10]     = 160

    __shared__ float s_Mu[H_][D_];
    __shared__ float s_mu2[H_];
    __shared__ float s_loss[16][H_];
    __shared__ int   s_best;

    const int bo   = blockIdx.x;
    const int b    = bo / O_;
    const int o    = bo % O_;
    const int tid  = threadIdx.x;
    const int lane = tid & 31;
    const int w    = tid >> 5;    // warp 0..15
    const int g    = tid >> 4;    // group 0..31
    const int d    = tid & 15;    // dim owned in phase 1
    const int is64 = g_is64;

    const float* ub = u + ((size_t)b * I_ * O_ + o) * D_;

    // ---- phase 0: load u slice + partial squared norms ----
    for (int e = tid; e < I_ * 4; e += T_) {
        int i = e >> 2, j = e & 3;
        float4 q = *(const float4*)(ub + (size_t)i * (O_ * D_) + j * 4);
        *(float4*)(s_u + i * D_ + j * 4) = q;
        s_scr[e] = q.x * q.x + q.y * q.y + q.z * q.z + q.w * q.w;
    }
    __syncthreads();
    for (int i = tid; i < I_; i += T_) {
        float s = s_scr[4 * i] + s_scr[4 * i + 1] + s_scr[4 * i + 2] + s_scr[4 * i + 3];
        s_vn[i] = sqrtf(s);
    }
    __syncthreads();

    // ---- phase 0b: build hypothesis bitmask in smem ----
    for (int i = tid; i < I_; i += T_) s_mask[i] = 0u;
    __syncthreads();
    for (int e = tid; e < S_ * H_; e += T_) {
        int s   = e / H_;
        int h   = e - s * H_;
        int off = ((b * S_ + s) * O_ + o) * H_ + h;
        int i   = is64 ? idx[2 * off] : idx[off];
        atomicOr(&s_mask[i], 1u << h);
    }
    __syncthreads();

    // ---- phase 1: masked weighted accumulation ----
    float acc[H_], den[H_];
#pragma unroll
    for (int h = 0; h < H_; h++) { acc[h] = 0.f; den[h] = 0.f; }

#pragma unroll 4
    for (int i = g; i < I_; i += 32) {            // 36 iters
        unsigned m  = s_mask[i];
        float    v  = s_vn[i];
        float    t0 = v * s_u[i * D_ + d];
#pragma unroll
        for (int h = 0; h < H_; h++) {
            if (m & (1u << h)) { acc[h] += t0; den[h] += v; }
        }
    }
    // combine the two 16-lane groups of each warp (same d, different i-set)
#pragma unroll
    for (int h = 0; h < H_; h++) {
        acc[h] += __shfl_down_sync(0xffffffffu, acc[h], 16);
        den[h] += __shfl_down_sync(0xffffffffu, den[h], 16);
    }
    if (lane < 16) {
#pragma unroll
        for (int h = 0; h < H_; h++) s_num[(w * H_ + h) * 16 + d] = acc[h];
        if (lane == 0) {
#pragma unroll
            for (int h = 0; h < H_; h++) s_den[w * H_ + h] = den[h];
        }
    }
    __syncthreads();

    if (tid < H_ * 16) {
        int h = tid >> 4, dd = tid & 15;
        float sn = 0.f, dn = 0.f;
#pragma unroll
        for (int ww = 0; ww < 16; ww++) {
            sn += s_num[(ww * H_ + h) * 16 + dd];
            dn += s_den[ww * H_ + h];
        }
        s_Mu[h][dd] = sn / dn;
    }
    __syncthreads();
    if (tid < H_) {
        float m2 = 0.f;
#pragma unroll
        for (int dd = 0; dd < 16; dd++) { float x = s_Mu[tid][dd]; m2 += x * x; }
        s_mu2[tid] = m2;
    }
    __syncthreads();

    // ---- phase 2: losses ----
    float loss[H_];
#pragma unroll
    for (int h = 0; h < H_; h++) loss[h] = 0.f;

    for (int i = tid; i < I_; i += T_) {
        const float4* p = (const float4*)(s_u + i * D_);
        float4 q0 = p[0], q1 = p[1], q2 = p[2], q3 = p[3];
        float  v  = s_vn[i];
        float  sq = v * v;
#pragma unroll
        for (int h = 0; h < H_; h++) {
            const float4* mp = (const float4*)&s_Mu[h][0];
            float4 m0 = mp[0], m1 = mp[1], m2 = mp[2], m3 = mp[3];
            float dot = q0.x * m0.x + q0.y * m0.y + q0.z * m0.z + q0.w * m0.w
                      + q1.x * m1.x + q1.y * m1.y + q1.z * m1.z + q1.w * m1.w
                      + q2.x * m2.x + q2.y * m2.y + q2.z * m2.z + q2.w * m2.w
                      + q3.x * m3.x + q3.y * m3.y + q3.z * m3.z + q3.w * m3.w;
            float val = sq + fmaf(-2.f, dot, s_mu2[h]);
            loss[h] += sqrtf(fmaxf(val, 0.f));
        }
    }

#pragma unroll
    for (int h = 0; h < H_; h++) {
#pragma unroll
        for (int off = 16; off > 0; off >>= 1)
            loss[h] += __shfl_down_sync(0xffffffffu, loss[h], off);
    }
    if (lane == 0) {
#pragma unroll
        for (int h = 0; h < H_; h++) s_loss[w][h] = loss[h];
    }
    __syncthreads();

    if (tid == 0) {
        float bestv = 3.4e38f;
        int   besth = 0;
#pragma unroll
        for (int h = 0; h < H_; h++) {
            float l = 0.f;
#pragma unroll
            for (int ww = 0; ww < 16; ww++) l += s_loss[ww][h];
            if (l < bestv) { bestv = l; besth = h; }
        }
        s_best = besth;
    }
    __syncthreads();

    if (tid < D_) out[(size_t)bo * D_ + tid] = s_Mu[s_best][tid];
}

// ---------------------------------------------------------------------------
extern "C" void kernel_launch(void* const* d_in, const int* in_sizes, int n_in,
                              void* d_out, int out_size) {
    const float* u   = (const float*)d_in[0];
    const int*   idx = (const int*)d_in[1];
    float*       out = (float*)d_out;
    (void)in_sizes; (void)n_in; (void)out_size;

    const int dynSmem = (I_ * D_ + I_ + 4608) * 4;   // 96768 bytes
    static int attr_set = 0;
    if (!attr_set) {
        cudaFuncSetAttribute(fused_kernel,
                             cudaFuncAttributeMaxDynamicSharedMemorySize, dynSmem);
        attr_set = 1;
    }

    detect_kernel<<<1, 256>>>((const unsigned*)idx);
    fused_kernel<<<B_ * O_, T_, dynSmem>>>(u, idx, out);
}

// round 4
// speedup vs baseline: 1.0558x; 1.0558x over previous
#include <cuda_runtime.h>
#include <cstdint>

#define B_ 32
#define I_ 1152
#define O_ 10
#define D_ 16
#define H_ 10
#define S_ 922
#define T_ 512
#define PAD 20          // s_u row stride in floats (16B-aligned, bank-conflict-free)

// ---------------------------------------------------------------------------
// One block per (b,o). All intermediates in shared memory. Phases:
//  0: detect int64 (warp0, SAFE: first 64 elems only), zero, load u -> s_u
//  0b: vn from s_u; vectorized idx gather -> smem atomicOr bitmask
//  1: masked weighted accumulation -> Mu numerators (5 acc/thread, no spills)
//  1b: den pass (10 warps); Mu = num/den; mu2
//  2: loss[h] = sum_i sqrt(vn^2 - 2 u.Mu + mu2), argmin, emit Mu[h*]
// Dynamic smem: u 1152*20*4 + vn 1152*4 + mask 1152*4 = 101376 B -> 2 blocks/SM
// ---------------------------------------------------------------------------
__global__ void __launch_bounds__(T_) fused_kernel(const float* __restrict__ u,
                                                   const int* __restrict__ idx,
                                                   float* __restrict__ out) {
    extern __shared__ float sm[];
    float*    s_u    = sm;                         // [1152][PAD]
    float*    s_vn   = sm + I_ * PAD;              // [1152]
    unsigned* s_mask = (unsigned*)(s_vn + I_);     // [1152]

    __shared__ float s_MuNum[H_ * D_];
    __shared__ float s_den[H_];
    __shared__ __align__(16) float s_Mu[H_][D_];
    __shared__ float s_mu2[H_];
    __shared__ float s_loss[16][H_];
    __shared__ int   s_best;
    __shared__ int   s_is64;

    const int bo   = blockIdx.x;
    const int b    = bo / O_;
    const int o    = bo % O_;
    const int tid  = threadIdx.x;
    const int lane = tid & 31;
    const int w    = tid >> 5;      // warp 0..15

    const float* ub = u + ((size_t)b * I_ * O_ + o) * D_;

    // ---- phase 0: dtype probe (SAFE: words 1..129 only) + zero + load u ----
    if (w == 0) {
        // If idx is int64, odd 32-bit words are 0 (values < 1152). Probe the
        // first 64 elements: within bounds for either dtype.
        unsigned v = ((const unsigned*)idx)[2 * lane + 1]
                   | ((const unsigned*)idx)[2 * (lane + 32) + 1];
        unsigned r = __reduce_or_sync(0xffffffffu, v);
        if (lane == 0) s_is64 = (r == 0u) ? 1 : 0;
    }
    for (int j = tid; j < I_; j += T_) s_mask[j] = 0u;
    if (tid < H_ * D_) s_MuNum[tid] = 0.f;

    for (int e = tid; e < I_ * 4; e += T_) {
        int i = e >> 2, j = e & 3;
        float4 q = *(const float4*)(ub + (size_t)i * (O_ * D_) + j * 4);
        *(float4*)(s_u + i * PAD + j * 4) = q;
    }
    __syncthreads();

    // ---- phase 0b: norms + vectorized gather/scatter ----
    for (int i = tid; i < I_; i += T_) {
        const float4* p = (const float4*)(s_u + i * PAD);
        float4 q0 = p[0], q1 = p[1], q2 = p[2], q3 = p[3];
        float s = q0.x * q0.x + q0.y * q0.y + q0.z * q0.z + q0.w * q0.w
                + q1.x * q1.x + q1.y * q1.y + q1.z * q1.z + q1.w * q1.w
                + q2.x * q2.x + q2.y * q2.y + q2.z * q2.z + q2.w * q2.w
                + q3.x * q3.x + q3.y * q3.y + q3.z * q3.z + q3.w * q3.w;
        s_vn[i] = sqrtf(s);
    }

    const int is64 = s_is64;
    if (is64) {
        for (int s = tid; s < S_; s += T_) {
            int base = ((b * S_ + s) * O_ + o) * H_;          // int64 elements; even
            const int4* p = (const int4*)idx + (base >> 1);   // 16B-aligned
            int4 a0 = p[0], a1 = p[1], a2 = p[2], a3 = p[3], a4 = p[4];
            atomicOr(&s_mask[a0.x], 1u << 0);
            atomicOr(&s_mask[a0.z], 1u << 1);
            atomicOr(&s_mask[a1.x], 1u << 2);
            atomicOr(&s_mask[a1.z], 1u << 3);
            atomicOr(&s_mask[a2.x], 1u << 4);
            atomicOr(&s_mask[a2.z], 1u << 5);
            atomicOr(&s_mask[a3.x], 1u << 6);
            atomicOr(&s_mask[a3.z], 1u << 7);
            atomicOr(&s_mask[a4.x], 1u << 8);
            atomicOr(&s_mask[a4.z], 1u << 9);
        }
    } else {
        for (int s = tid; s < S_; s += T_) {
            int base = ((b * S_ + s) * O_ + o) * H_;          // int32 elements; even
            const int2* p = (const int2*)idx + (base >> 1);   // 8B-aligned
            int2 a0 = p[0], a1 = p[1], a2 = p[2], a3 = p[3], a4 = p[4];
            atomicOr(&s_mask[a0.x], 1u << 0);
            atomicOr(&s_mask[a0.y], 1u << 1);
            atomicOr(&s_mask[a1.x], 1u << 2);
            atomicOr(&s_mask[a1.y], 1u << 3);
            atomicOr(&s_mask[a2.x], 1u << 4);
            atomicOr(&s_mask[a2.y], 1u << 5);
            atomicOr(&s_mask[a3.x], 1u << 6);
            atomicOr(&s_mask[a3.y], 1u << 7);
            atomicOr(&s_mask[a4.x], 1u << 8);
            atomicOr(&s_mask[a4.y], 1u << 9);
        }
    }
    __syncthreads();

    // ---- phase 1: masked accumulation (warp = i-stripe; lane halves = h-halves) ----
    {
        const int d  = lane & 15;
        const int hb = (lane >> 4) * 5;       // 0 or 5
        float a0 = 0.f, a1 = 0.f, a2 = 0.f, a3 = 0.f, a4 = 0.f;
#pragma unroll 4
        for (int i = w; i < I_; i += 16) {    // 72 iterations
            unsigned m  = s_mask[i] >> hb;    // broadcast load
            float    t0 = s_vn[i] * s_u[i * PAD + d];
            if (m & 1u)  a0 += t0;
            if (m & 2u)  a1 += t0;
            if (m & 4u)  a2 += t0;
            if (m & 8u)  a3 += t0;
            if (m & 16u) a4 += t0;
        }
        atomicAdd(&s_MuNum[(hb + 0) * D_ + d], a0);
        atomicAdd(&s_MuNum[(hb + 1) * D_ + d], a1);
        atomicAdd(&s_MuNum[(hb + 2) * D_ + d], a2);
        atomicAdd(&s_MuNum[(hb + 3) * D_ + d], a3);
        atomicAdd(&s_MuNum[(hb + 4) * D_ + d], a4);
    }

    // ---- phase 1b: den pass (10 warps, one h each) ----
    if (w < H_) {
        unsigned bit = 1u << w;
        float dn = 0.f;
#pragma unroll 4
        for (int i = lane; i < I_; i += 32)
            if (s_mask[i] & bit) dn += s_vn[i];
#pragma unroll
        for (int off = 16; off > 0; off >>= 1)
            dn += __shfl_down_sync(0xffffffffu, dn, off);
        if (lane == 0) s_den[w] = dn;
    }
    __syncthreads();

    if (tid < H_ * D_) {
        int h = tid >> 4;
        s_Mu[h][tid & 15] = s_MuNum[tid] / s_den[h];
    }
    __syncthreads();
    if (tid < H_) {
        float m2 = 0.f;
#pragma unroll
        for (int dd = 0; dd < D_; dd++) { float x = s_Mu[tid][dd]; m2 += x * x; }
        s_mu2[tid] = m2;
    }
    __syncthreads();

    // ---- phase 2: losses ----
    float loss[H_];
#pragma unroll
    for (int h = 0; h < H_; h++) loss[h] = 0.f;

    for (int i = tid; i < I_; i += T_) {
        const float4* p = (const float4*)(s_u + i * PAD);
        float4 q0 = p[0], q1 = p[1], q2 = p[2], q3 = p[3];
        float  v  = s_vn[i];
        float  sq = v * v;
#pragma unroll
        for (int h = 0; h < H_; h++) {
            const float4* mp = (const float4*)&s_Mu[h][0];   // broadcast
            float4 m0 = mp[0], m1 = mp[1], m2 = mp[2], m3 = mp[3];
            float dot = q0.x * m0.x + q0.y * m0.y + q0.z * m0.z + q0.w * m0.w
                      + q1.x * m1.x + q1.y * m1.y + q1.z * m1.z + q1.w * m1.w
                      + q2.x * m2.x + q2.y * m2.y + q2.z * m2.z + q2.w * m2.w
                      + q3.x * m3.x + q3.y * m3.y + q3.z * m3.z + q3.w * m3.w;
            float val = sq + fmaf(-2.f, dot, s_mu2[h]);
            loss[h] += sqrtf(fmaxf(val, 0.f));
        }
    }

#pragma unroll
    for (int h = 0; h < H_; h++) {
#pragma unroll
        for (int off = 16; off > 0; off >>= 1)
            loss[h] += __shfl_down_sync(0xffffffffu, loss[h], off);
    }
    if (lane == 0) {
#pragma unroll
        for (int h = 0; h < H_; h++) s_loss[w][h] = loss[h];
    }
    __syncthreads();

    if (tid == 0) {
        float bestv = 3.4e38f;
        int   besth = 0;
#pragma unroll
        for (int h = 0; h < H_; h++) {
            float l = 0.f;
#pragma unroll
            for (int ww = 0; ww < 16; ww++) l += s_loss[ww][h];
            if (l < bestv) { bestv = l; besth = h; }
        }
        s_best = besth;
    }
    __syncthreads();

    if (tid < D_) out[(size_t)bo * D_ + tid] = s_Mu[s_best][tid];
}

// ---------------------------------------------------------------------------
extern "C" void kernel_launch(void* const* d_in, const int* in_sizes, int n_in,
                              void* d_out, int out_size) {
    const float* u   = (const float*)d_in[0];
    const int*   idx = (const int*)d_in[1];
    float*       out = (float*)d_out;
    (void)in_sizes; (void)n_in; (void)out_size;

    const int dynSmem = (I_ * PAD + I_ + I_) * 4;   // 101376 bytes
    static int attr_set = 0;
    if (!attr_set) {
        cudaFuncSetAttribute(fused_kernel,
                             cudaFuncAttributeMaxDynamicSharedMemorySize, dynSmem);
        attr_set = 1;
    }
    fused_kernel<<<B_ * O_, T_, dynSmem>>>(u, idx, out);
}

// round 5
// speedup vs baseline: 1.4593x; 1.3822x over previous
#include <cuda_runtime.h>
#include <cstdint>

#define B_ 32
#define I_ 1152
#define O_ 10
#define D_ 16
#define H_ 10
#define S_ 922
#define T_ 512
#define PAD 20          // s_u row stride in floats (16B-aligned, bank-conflict-free)

// ---------------------------------------------------------------------------
// One block per (b,o). All intermediates in shared memory.
//  0:  dtype probe (safe: first 64 elems), zero, load u -> s_u
//  0b: vn from s_u; vectorized idx gather -> smem atomicOr bitmask
//  1:  masked weighted accumulation -> Mu numerators (5 acc/thread)
//  1b: den pass (10 warps); Mu = num/den; mu2
//  2:  loss in TWO passes of 5 hypotheses (peak live regs ~30 < 64 cap)
//  argmin, emit Mu[h*]
// Dynamic smem: 1152*(20+1+1)*4 = 101376 B -> 2 blocks/SM (explicit in bounds)
// ---------------------------------------------------------------------------
__global__ void __launch_bounds__(T_, 2) fused_kernel(const float* __restrict__ u,
                                                      const int* __restrict__ idx,
                                                      float* __restrict__ out) {
    extern __shared__ float sm[];
    float*    s_u    = sm;                         // [1152][PAD]
    float*    s_vn   = sm + I_ * PAD;              // [1152]
    unsigned* s_mask = (unsigned*)(s_vn + I_);     // [1152]

    __shared__ float s_MuNum[H_ * D_];
    __shared__ float s_den[H_];
    __shared__ __align__(16) float s_Mu[H_][D_];
    __shared__ float s_mu2[H_];
    __shared__ float s_loss[16][H_];
    __shared__ int   s_best;
    __shared__ int   s_is64;

    const int bo   = blockIdx.x;
    const int b    = bo / O_;
    const int o    = bo % O_;
    const int tid  = threadIdx.x;
    const int lane = tid & 31;
    const int w    = tid >> 5;      // warp 0..15

    const float* ub = u + ((size_t)b * I_ * O_ + o) * D_;

    // ---- phase 0: dtype probe + zero + load u ----
    if (w == 0) {
        unsigned v = ((const unsigned*)idx)[2 * lane + 1]
                   | ((const unsigned*)idx)[2 * (lane + 32) + 1];
        unsigned r = __reduce_or_sync(0xffffffffu, v);
        if (lane == 0) s_is64 = (r == 0u) ? 1 : 0;
    }
    for (int j = tid; j < I_; j += T_) s_mask[j] = 0u;
    if (tid < H_ * D_) s_MuNum[tid] = 0.f;

    for (int e = tid; e < I_ * 4; e += T_) {
        int i = e >> 2, j = e & 3;
        float4 q = *(const float4*)(ub + (size_t)i * (O_ * D_) + j * 4);
        *(float4*)(s_u + i * PAD + j * 4) = q;
    }
    __syncthreads();

    // ---- phase 0b: norms + vectorized gather/scatter ----
    for (int i = tid; i < I_; i += T_) {
        const float4* p = (const float4*)(s_u + i * PAD);
        float4 q0 = p[0], q1 = p[1], q2 = p[2], q3 = p[3];
        float s = q0.x * q0.x + q0.y * q0.y + q0.z * q0.z + q0.w * q0.w
                + q1.x * q1.x + q1.y * q1.y + q1.z * q1.z + q1.w * q1.w
                + q2.x * q2.x + q2.y * q2.y + q2.z * q2.z + q2.w * q2.w
                + q3.x * q3.x + q3.y * q3.y + q3.z * q3.z + q3.w * q3.w;
        s_vn[i] = sqrtf(s);
    }

    if (s_is64) {
        for (int s = tid; s < S_; s += T_) {
            int base = ((b * S_ + s) * O_ + o) * H_;
            const int4* p = (const int4*)idx + (base >> 1);
            int4 a0 = p[0], a1 = p[1], a2 = p[2], a3 = p[3], a4 = p[4];
            atomicOr(&s_mask[a0.x], 1u << 0);
            atomicOr(&s_mask[a0.z], 1u << 1);
            atomicOr(&s_mask[a1.x], 1u << 2);
            atomicOr(&s_mask[a1.z], 1u << 3);
            atomicOr(&s_mask[a2.x], 1u << 4);
            atomicOr(&s_mask[a2.z], 1u << 5);
            atomicOr(&s_mask[a3.x], 1u << 6);
            atomicOr(&s_mask[a3.z], 1u << 7);
            atomicOr(&s_mask[a4.x], 1u << 8);
            atomicOr(&s_mask[a4.z], 1u << 9);
        }
    } else {
        for (int s = tid; s < S_; s += T_) {
            int base = ((b * S_ + s) * O_ + o) * H_;
            const int2* p = (const int2*)idx + (base >> 1);
            int2 a0 = p[0], a1 = p[1], a2 = p[2], a3 = p[3], a4 = p[4];
            atomicOr(&s_mask[a0.x], 1u << 0);
            atomicOr(&s_mask[a0.y], 1u << 1);
            atomicOr(&s_mask[a1.x], 1u << 2);
            atomicOr(&s_mask[a1.y], 1u << 3);
            atomicOr(&s_mask[a2.x], 1u << 4);
            atomicOr(&s_mask[a2.y], 1u << 5);
            atomicOr(&s_mask[a3.x], 1u << 6);
            atomicOr(&s_mask[a3.y], 1u << 7);
            atomicOr(&s_mask[a4.x], 1u << 8);
            atomicOr(&s_mask[a4.y], 1u << 9);
        }
    }
    __syncthreads();

    // ---- phase 1: masked accumulation (warp = i-stripe; lane halves = h-halves) ----
    {
        const int d  = lane & 15;
        const int hb = (lane >> 4) * 5;       // 0 or 5
        float a0 = 0.f, a1 = 0.f, a2 = 0.f, a3 = 0.f, a4 = 0.f;
#pragma unroll 4
        for (int i = w; i < I_; i += 16) {    // 72 iterations
            unsigned m  = s_mask[i] >> hb;
            float    t0 = s_vn[i] * s_u[i * PAD + d];
            if (m & 1u)  a0 += t0;
            if (m & 2u)  a1 += t0;
            if (m & 4u)  a2 += t0;
            if (m & 8u)  a3 += t0;
            if (m & 16u) a4 += t0;
        }
        atomicAdd(&s_MuNum[(hb + 0) * D_ + d], a0);
        atomicAdd(&s_MuNum[(hb + 1) * D_ + d], a1);
        atomicAdd(&s_MuNum[(hb + 2) * D_ + d], a2);
        atomicAdd(&s_MuNum[(hb + 3) * D_ + d], a3);
        atomicAdd(&s_MuNum[(hb + 4) * D_ + d], a4);
    }

    // ---- phase 1b: den pass (10 warps, one h each) ----
    if (w < H_) {
        unsigned bit = 1u << w;
        float dn = 0.f;
#pragma unroll 4
        for (int i = lane; i < I_; i += 32)
            if (s_mask[i] & bit) dn += s_vn[i];
#pragma unroll
        for (int off = 16; off > 0; off >>= 1)
            dn += __shfl_down_sync(0xffffffffu, dn, off);
        if (lane == 0) s_den[w] = dn;
    }
    __syncthreads();

    if (tid < H_ * D_) {
        int h = tid >> 4;
        s_Mu[h][tid & 15] = s_MuNum[tid] / s_den[h];
    }
    __syncthreads();
    if (tid < H_) {
        float m2 = 0.f;
#pragma unroll
        for (int dd = 0; dd < D_; dd++) { float x = s_Mu[tid][dd]; m2 += x * x; }
        s_mu2[tid] = m2;
    }
    __syncthreads();

    // ---- phase 2: losses in TWO passes of 5 h (keeps live regs < 64) ----
#pragma unroll 1
    for (int pass = 0; pass < 2; pass++) {
        const int hb = pass * 5;
        float l0 = 0.f, l1 = 0.f, l2 = 0.f, l3 = 0.f, l4 = 0.f;
        for (int i = tid; i < I_; i += T_) {
            const float4* p = (const float4*)(s_u + i * PAD);
            float4 q0 = p[0], q1 = p[1], q2 = p[2], q3 = p[3];
            float  v  = s_vn[i];
            float  sq = v * v;
#pragma unroll
            for (int hh = 0; hh < 5; hh++) {
                const float4* mp = (const float4*)&s_Mu[hb + hh][0];  // broadcast
                float4 m0 = mp[0], m1 = mp[1], m2 = mp[2], m3 = mp[3];
                float dot = q0.x * m0.x + q0.y * m0.y + q0.z * m0.z + q0.w * m0.w
                          + q1.x * m1.x + q1.y * m1.y + q1.z * m1.z + q1.w * m1.w
                          + q2.x * m2.x + q2.y * m2.y + q2.z * m2.z + q2.w * m2.w
                          + q3.x * m3.x + q3.y * m3.y + q3.z * m3.z + q3.w * m3.w;
                float val = sqrtf(fmaxf(sq + fmaf(-2.f, dot, s_mu2[hb + hh]), 0.f));
                if (hh == 0) l0 += val;
                else if (hh == 1) l1 += val;
                else if (hh == 2) l2 += val;
                else if (hh == 3) l3 += val;
                else l4 += val;
            }
        }
#pragma unroll
        for (int off = 16; off > 0; off >>= 1) {
            l0 += __shfl_down_sync(0xffffffffu, l0, off);
            l1 += __shfl_down_sync(0xffffffffu, l1, off);
            l2 += __shfl_down_sync(0xffffffffu, l2, off);
            l3 += __shfl_down_sync(0xffffffffu, l3, off);
            l4 += __shfl_down_sync(0xffffffffu, l4, off);
        }
        if (lane == 0) {
            s_loss[w][hb + 0] = l0;
            s_loss[w][hb + 1] = l1;
            s_loss[w][hb + 2] = l2;
            s_loss[w][hb + 3] = l3;
            s_loss[w][hb + 4] = l4;
        }
    }
    __syncthreads();

    if (tid == 0) {
        float bestv = 3.4e38f;
        int   besth = 0;
#pragma unroll
        for (int h = 0; h < H_; h++) {
            float l = 0.f;
#pragma unroll
            for (int ww = 0; ww < 16; ww++) l += s_loss[ww][h];
            if (l < bestv) { bestv = l; besth = h; }
        }
        s_best = besth;
    }
    __syncthreads();

    if (tid < D_) out[(size_t)bo * D_ + tid] = s_Mu[s_best][tid];
}

// ---------------------------------------------------------------------------
extern "C" void kernel_launch(void* const* d_in, const int* in_sizes, int n_in,
                              void* d_out, int out_size) {
    const float* u   = (const float*)d_in[0];
    const int*   idx = (const int*)d_in[1];
    float*       out = (float*)d_out;
    (void)in_sizes; (void)n_in; (void)out_size;

    const int dynSmem = (I_ * PAD + I_ + I_) * 4;   // 101376 bytes
    static int attr_set = 0;
    if (!attr_set) {
        cudaFuncSetAttribute(fused_kernel,
                             cudaFuncAttributeMaxDynamicSharedMemorySize, dynSmem);
        attr_set = 1;
    }
    fused_kernel<<<B_ * O_, T_, dynSmem>>>(u, idx, out);
}

// round 6
// speedup vs baseline: 2.2001x; 1.5076x over previous
#include <cuda_runtime.h>
#include <cstdint>

#define B_ 32
#define I_ 1152
#define O_ 10
#define D_ 16
#define H_ 10
#define S_ 922
#define T_ 512
#define PAD 20          // s_u row stride in floats (16B-aligned, bank-conflict-free)

// ---------------------------------------------------------------------------
// One block per (b,o). All intermediates in shared memory.
//  0:  dtype probe (safe: first 64 elems), zero, load u -> s_u
//  0b: vn from s_u; vectorized idx gather -> smem atomicOr bitmask
//  1:  masked weighted accumulation -> Mu numerators (5 acc/thread)
//  1b: den pass (10 warps); Mu = num/den; mu2
//  2:  loss: thread quad owns a d-quarter (float4 q), dot via 2x shfl.bfly;
//      all 4 lanes add the same sqrt -> loss uniformly x4, argmin invariant
//  argmin, emit Mu[h*]
// Dynamic smem: 1152*(20+1+1)*4 = 101376 B -> 2 blocks/SM
// ---------------------------------------------------------------------------
__global__ void __launch_bounds__(T_, 2) fused_kernel(const float* __restrict__ u,
                                                      const int* __restrict__ idx,
                                                      float* __restrict__ out) {
    extern __shared__ float sm[];
    float*    s_u    = sm;                         // [1152][PAD]
    float*    s_vn   = sm + I_ * PAD;              // [1152]
    unsigned* s_mask = (unsigned*)(s_vn + I_);     // [1152]

    __shared__ float s_MuNum[H_ * D_];
    __shared__ float s_den[H_];
    __shared__ __align__(16) float s_Mu[H_][D_];
    __shared__ float s_mu2[H_];
    __shared__ float s_loss[16][H_];
    __shared__ int   s_best;
    __shared__ int   s_is64;

    const int bo   = blockIdx.x;
    const int b    = bo / O_;
    const int o    = bo % O_;
    const int tid  = threadIdx.x;
    const int lane = tid & 31;
    const int w    = tid >> 5;      // warp 0..15

    const float* ub = u + ((size_t)b * I_ * O_ + o) * D_;

    // ---- phase 0: dtype probe + zero + load u ----
    if (w == 0) {
        unsigned v = ((const unsigned*)idx)[2 * lane + 1]
                   | ((const unsigned*)idx)[2 * (lane + 32) + 1];
        unsigned r = __reduce_or_sync(0xffffffffu, v);
        if (lane == 0) s_is64 = (r == 0u) ? 1 : 0;
    }
    for (int j = tid; j < I_; j += T_) s_mask[j] = 0u;
    if (tid < H_ * D_) s_MuNum[tid] = 0.f;

    for (int e = tid; e < I_ * 4; e += T_) {
        int i = e >> 2, j = e & 3;
        float4 q = *(const float4*)(ub + (size_t)i * (O_ * D_) + j * 4);
        *(float4*)(s_u + i * PAD + j * 4) = q;
    }
    __syncthreads();

    // ---- phase 0b: norms + vectorized gather/scatter ----
    for (int i = tid; i < I_; i += T_) {
        const float4* p = (const float4*)(s_u + i * PAD);
        float4 q0 = p[0], q1 = p[1], q2 = p[2], q3 = p[3];
        float s = q0.x * q0.x + q0.y * q0.y + q0.z * q0.z + q0.w * q0.w
                + q1.x * q1.x + q1.y * q1.y + q1.z * q1.z + q1.w * q1.w
                + q2.x * q2.x + q2.y * q2.y + q2.z * q2.z + q2.w * q2.w
                + q3.x * q3.x + q3.y * q3.y + q3.z * q3.z + q3.w * q3.w;
        s_vn[i] = sqrtf(s);
    }

    if (s_is64) {
#pragma unroll 1
        for (int s = tid; s < S_; s += T_) {
            int base = ((b * S_ + s) * O_ + o) * H_;
            const int4* p = (const int4*)idx + (base >> 1);
            int4 a0 = p[0], a1 = p[1], a2 = p[2], a3 = p[3], a4 = p[4];
            atomicOr(&s_mask[a0.x], 1u << 0);
            atomicOr(&s_mask[a0.z], 1u << 1);
            atomicOr(&s_mask[a1.x], 1u << 2);
            atomicOr(&s_mask[a1.z], 1u << 3);
            atomicOr(&s_mask[a2.x], 1u << 4);
            atomicOr(&s_mask[a2.z], 1u << 5);
            atomicOr(&s_mask[a3.x], 1u << 6);
            atomicOr(&s_mask[a3.z], 1u << 7);
            atomicOr(&s_mask[a4.x], 1u << 8);
            atomicOr(&s_mask[a4.z], 1u << 9);
        }
    } else {
#pragma unroll 1
        for (int s = tid; s < S_; s += T_) {
            int base = ((b * S_ + s) * O_ + o) * H_;
            const int2* p = (const int2*)idx + (base >> 1);
            int2 a0 = p[0], a1 = p[1], a2 = p[2], a3 = p[3], a4 = p[4];
            atomicOr(&s_mask[a0.x], 1u << 0);
            atomicOr(&s_mask[a0.y], 1u << 1);
            atomicOr(&s_mask[a1.x], 1u << 2);
            atomicOr(&s_mask[a1.y], 1u << 3);
            atomicOr(&s_mask[a2.x], 1u << 4);
            atomicOr(&s_mask[a2.y], 1u << 5);
            atomicOr(&s_mask[a3.x], 1u << 6);
            atomicOr(&s_mask[a3.y], 1u << 7);
            atomicOr(&s_mask[a4.x], 1u << 8);
            atomicOr(&s_mask[a4.y], 1u << 9);
        }
    }
    __syncthreads();

    // ---- phase 1: masked accumulation (warp = i-stripe; lane halves = h-halves) ----
    {
        const int d  = lane & 15;
        const int hb = (lane >> 4) * 5;       // 0 or 5
        float a0 = 0.f, a1 = 0.f, a2 = 0.f, a3 = 0.f, a4 = 0.f;
#pragma unroll 4
        for (int i = w; i < I_; i += 16) {    // 72 iterations
            unsigned m  = s_mask[i] >> hb;
            float    t0 = s_vn[i] * s_u[i * PAD + d];
            if (m & 1u)  a0 += t0;
            if (m & 2u)  a1 += t0;
            if (m & 4u)  a2 += t0;
            if (m & 8u)  a3 += t0;
            if (m & 16u) a4 += t0;
        }
        atomicAdd(&s_MuNum[(hb + 0) * D_ + d], a0);
        atomicAdd(&s_MuNum[(hb + 1) * D_ + d], a1);
        atomicAdd(&s_MuNum[(hb + 2) * D_ + d], a2);
        atomicAdd(&s_MuNum[(hb + 3) * D_ + d], a3);
        atomicAdd(&s_MuNum[(hb + 4) * D_ + d], a4);
    }

    // ---- phase 1b: den pass (10 warps, one h each) ----
    if (w < H_) {
        unsigned bit = 1u << w;
        float dn = 0.f;
#pragma unroll 4
        for (int i = lane; i < I_; i += 32)
            if (s_mask[i] & bit) dn += s_vn[i];
#pragma unroll
        for (int off = 16; off > 0; off >>= 1)
            dn += __shfl_down_sync(0xffffffffu, dn, off);
        if (lane == 0) s_den[w] = dn;
    }
    __syncthreads();

    if (tid < H_ * D_) {
        int h = tid >> 4;
        s_Mu[h][tid & 15] = s_MuNum[tid] / s_den[h];
    }
    __syncthreads();
    if (tid < H_) {
        float m2 = 0.f;
#pragma unroll
        for (int dd = 0; dd < D_; dd++) { float x = s_Mu[tid][dd]; m2 += x * x; }
        s_mu2[tid] = m2;
    }
    __syncthreads();

    // ---- phase 2: losses, d-quarter per thread (low register pressure) ----
    {
        const int dq = tid & 3;               // d-quarter owned
        const int g  = tid >> 2;              // 0..127 (i-group)
        float loss[H_];
#pragma unroll
        for (int h = 0; h < H_; h++) loss[h] = 0.f;

#pragma unroll 1
        for (int k = 0; k < I_ / 128; k++) {  // 9 iterations
            int i = g + k * 128;
            float4 q = *(const float4*)(s_u + i * PAD + dq * 4);
            float  v = s_vn[i];
            float sq = v * v;
#pragma unroll
            for (int h = 0; h < H_; h++) {
                float4 m = *(const float4*)(&s_Mu[h][dq * 4]);
                float dot = q.x * m.x + q.y * m.y + q.z * m.z + q.w * m.w;
                dot += __shfl_xor_sync(0xffffffffu, dot, 1);
                dot += __shfl_xor_sync(0xffffffffu, dot, 2);
                float val = sq + fmaf(-2.f, dot, s_mu2[h]);
                loss[h] += sqrtf(fmaxf(val, 0.f));   // x4 per i (all quad lanes)
            }
        }
        // warp reduce (totals are uniformly 4x true loss -> argmin unaffected)
#pragma unroll
        for (int h = 0; h < H_; h++) {
#pragma unroll
            for (int off = 16; off > 0; off >>= 1)
                loss[h] += __shfl_down_sync(0xffffffffu, loss[h], off);
        }
        if (lane == 0) {
#pragma unroll
            for (int h = 0; h < H_; h++) s_loss[w][h] = loss[h];
        }
    }
    __syncthreads();

    if (tid == 0) {
        float bestv = 3.4e38f;
        int   besth = 0;
#pragma unroll
        for (int h = 0; h < H_; h++) {
            float l = 0.f;
#pragma unroll
            for (int ww = 0; ww < 16; ww++) l += s_loss[ww][h];
            if (l < bestv) { bestv = l; besth = h; }
        }
        s_best = besth;
    }
    __syncthreads();

    if (tid < D_) out[(size_t)bo * D_ + tid] = s_Mu[s_best][tid];
}

// ---------------------------------------------------------------------------
extern "C" void kernel_launch(void* const* d_in, const int* in_sizes, int n_in,
                              void* d_out, int out_size) {
    const float* u   = (const float*)d_in[0];
    const int*   idx = (const int*)d_in[1];
    float*       out = (float*)d_out;
    (void)in_sizes; (void)n_in; (void)out_size;

    const int dynSmem = (I_ * PAD + I_ + I_) * 4;   // 101376 bytes
    static int attr_set = 0;
    if (!attr_set) {
        cudaFuncSetAttribute(fused_kernel,
                             cudaFuncAttributeMaxDynamicSharedMemorySize, dynSmem);
        attr_set = 1;
    }
    fused_kernel<<<B_ * O_, T_, dynSmem>>>(u, idx, out);
}